// round 4
// baseline (speedup 1.0000x reference)
#include <cuda_runtime.h>
#include <mma.h>

using namespace nvcuda;

#define N_NODES 50000
#define N_PAD   50048          // 782 * 64, padded for guard-free wmma stores
#define N_EDGES 800000
#define DIN     64
#define DH      128
#define EPSI    1e-5f
#define SLOPE   0.1f

// ---------------- scratch (device globals; no allocations) ----------------
__device__ float g_deg   [N_NODES];
__device__ float g_dinv  [N_NODES];
__device__ int   g_count [N_NODES];
__device__ int   g_cursor[N_NODES];
__device__ int   g_off   [N_NODES + 1];
__device__ int   g_bsum  [256];          // block partial sums for scan
__device__ int   g_csr_src[N_EDGES];
__device__ float g_csr_w  [N_EDGES];
__device__ float g_h   [N_PAD * DH];     // linear-transform output
__device__ float g_agg [N_PAD * DH];     // aggregated messages
__device__ float g_res [N_PAD * DH];     // residual projection (no bias)
__device__ float g_act [N_PAD * DH];     // post-activation layer output (pad rows stay 0)
__device__ float g_stats[2 * DH];        // colsum / colsumsq
__device__ float g_ab   [2 * DH];        // BN scale a / shift c

// ---------------- init ----------------
__global__ void init_kernel() {
    int i = blockIdx.x * blockDim.x + threadIdx.x;
    if (i < N_NODES) {
        g_deg[i] = 1.0f;
        g_count[i] = 0;
        g_cursor[i] = 0;
    }
}

__global__ void edge_count_kernel(const int* __restrict__ dst,
                                  const float* __restrict__ ew) {
    int e = blockIdx.x * blockDim.x + threadIdx.x;
    if (e < N_EDGES) {
        int d = dst[e];
        atomicAdd(&g_deg[d], ew[e]);
        atomicAdd(&g_count[d], 1);
    }
}

__global__ void dinv_kernel() {
    int i = blockIdx.x * blockDim.x + threadIdx.x;
    if (i < N_NODES) {
        float d = g_deg[i];
        g_dinv[i] = d > 0.0f ? rsqrtf(d) : 0.0f;
    }
}

// ---------------- multi-block exclusive scan of counts ----------------
// Pass 1: per-block sums of 256 counts each (196 blocks)
__global__ void scan_pass1_kernel() {
    int i = blockIdx.x * 256 + threadIdx.x;
    int v = (i < N_NODES) ? g_count[i] : 0;
    #pragma unroll
    for (int off = 16; off > 0; off >>= 1)
        v += __shfl_xor_sync(0xffffffffu, v, off);
    __shared__ int ws[8];
    if ((threadIdx.x & 31) == 0) ws[threadIdx.x >> 5] = v;
    __syncthreads();
    if (threadIdx.x == 0) {
        int s = 0;
        #pragma unroll
        for (int w = 0; w < 8; w++) s += ws[w];
        g_bsum[blockIdx.x] = s;
    }
}

// Pass 2: single block exclusive-scans the (<=256) block sums in place
__global__ void scan_pass2_kernel(int nblocks) {
    __shared__ int sm[256];
    int t = threadIdx.x;
    int v = (t < nblocks) ? g_bsum[t] : 0;
    sm[t] = v;
    __syncthreads();
    for (int off = 1; off < 256; off <<= 1) {
        int u = (t >= off) ? sm[t - off] : 0;
        __syncthreads();
        sm[t] += u;
        __syncthreads();
    }
    if (t < nblocks) g_bsum[t] = sm[t] - v;   // exclusive
}

// Pass 3: intra-block scan + base -> offsets
__global__ void scan_pass3_kernel() {
    int t = threadIdx.x;
    int i = blockIdx.x * 256 + t;
    int v = (i < N_NODES) ? g_count[i] : 0;
    // warp inclusive scan
    int incl = v;
    #pragma unroll
    for (int off = 1; off < 32; off <<= 1) {
        int u = __shfl_up_sync(0xffffffffu, incl, off);
        if ((t & 31) >= off) incl += u;
    }
    __shared__ int ws[8];
    if ((t & 31) == 31) ws[t >> 5] = incl;
    __syncthreads();
    if (t < 32) {
        int wv = (t < 8) ? ws[t] : 0;
        #pragma unroll
        for (int off = 1; off < 8; off <<= 1) {
            int u = __shfl_up_sync(0xffffffffu, wv, off);
            if (t >= off) wv += u;
        }
        if (t < 8) ws[t] = wv;
    }
    __syncthreads();
    int warpBase = (t >= 32) ? ws[(t >> 5) - 1] : 0;
    int excl = g_bsum[blockIdx.x] + warpBase + incl - v;
    if (i <= N_NODES) g_off[i] = excl;   // i==N_NODES gets the grand total
}

// ---------------- fill CSR ----------------
__global__ void fill_kernel(const int* __restrict__ src,
                            const int* __restrict__ dst,
                            const float* __restrict__ ew) {
    int e = blockIdx.x * blockDim.x + threadIdx.x;
    if (e >= N_EDGES) return;
    int s = src[e];
    int d = dst[e];
    int pos = g_off[d] + atomicAdd(&g_cursor[d], 1);
    g_csr_src[pos] = s;
    g_csr_w[pos] = g_dinv[s] * ew[e] * g_dinv[d];
}

// ---------------- tf32 tensor-core GEMM with error correction ----------------
// C[M_pad,128] = A[M,K] @ B[K,128]; A split hi/lo, B split hi/lo, 3 mmas.
// Block tile 64x128, 8 warps (4 row x 2 col), warp tile 16x64.
template <int K>
__global__ __launch_bounds__(256)
void gemm_tc_kernel(const float* __restrict__ A, const float* __restrict__ B,
                    float* __restrict__ C, int M) {
    __shared__ float As[64 * K];

    int tid = threadIdx.x;
    int rowBase = blockIdx.x * 64;

    // stage A tile (64 x K) with row guard
    constexpr int VEC_PER_TILE = 64 * K / 4;
    #pragma unroll
    for (int v = tid; v < VEC_PER_TILE; v += 256) {
        int r = v / (K / 4);
        int c = v % (K / 4);
        float4 av = make_float4(0.f, 0.f, 0.f, 0.f);
        int gr = rowBase + r;
        if (gr < M) av = *(const float4*)(A + (long)gr * K + c * 4);
        *(float4*)(As + r * K + c * 4) = av;
    }
    __syncthreads();

    int w = tid >> 5;
    int wr = w & 3;          // 0..3 -> m offset
    int wc = w >> 2;         // 0..1 -> n offset (64 cols each)
    int m0 = wr * 16;
    int n0 = wc * 64;

    wmma::fragment<wmma::accumulator, 16, 16, 8, float> acc[4];
    #pragma unroll
    for (int t = 0; t < 4; t++) wmma::fill_fragment(acc[t], 0.0f);

    #pragma unroll
    for (int k0 = 0; k0 < K; k0 += 8) {
        wmma::fragment<wmma::matrix_a, 16, 16, 8, wmma::precision::tf32, wmma::row_major> a_hi, a_lo;
        wmma::load_matrix_sync(a_hi, As + m0 * K + k0, K);
        #pragma unroll
        for (int e = 0; e < a_hi.num_elements; e++) {
            float v = a_hi.x[e];
            float h = wmma::__float_to_tf32(v);
            a_hi.x[e] = h;
            a_lo.x[e] = wmma::__float_to_tf32(v - h);
        }
        #pragma unroll
        for (int t = 0; t < 4; t++) {
            wmma::fragment<wmma::matrix_b, 16, 16, 8, wmma::precision::tf32, wmma::row_major> b_hi, b_lo;
            wmma::load_matrix_sync(b_hi, B + k0 * DH + n0 + t * 16, DH);
            #pragma unroll
            for (int e = 0; e < b_hi.num_elements; e++) {
                float v = b_hi.x[e];
                float h = wmma::__float_to_tf32(v);
                b_hi.x[e] = h;
                b_lo.x[e] = wmma::__float_to_tf32(v - h);
            }
            wmma::mma_sync(acc[t], a_lo, b_hi, acc[t]);
            wmma::mma_sync(acc[t], a_hi, b_lo, acc[t]);
            wmma::mma_sync(acc[t], a_hi, b_hi, acc[t]);
        }
    }

    // guard-free store into padded C
    #pragma unroll
    for (int t = 0; t < 4; t++)
        wmma::store_matrix_sync(C + (long)(rowBase + m0) * DH + n0 + t * 16,
                                acc[t], DH, wmma::mem_row_major);
}

// ---------------- fused aggregation: self-loop + bias + gather + BN stats -----
__global__ __launch_bounds__(256)
void aggregate_kernel(const float* __restrict__ h,
                      const float* __restrict__ bias,
                      float* __restrict__ agg) {
    __shared__ float s_sum[DH];
    __shared__ float s_sq [DH];
    int tid = threadIdx.x;
    if (tid < DH) { s_sum[tid] = 0.0f; s_sq[tid] = 0.0f; }
    __syncthreads();

    int node = blockIdx.x * 8 + (tid >> 5);
    int lane = tid & 31;
    const float4* h4 = (const float4*)h;

    float di = g_dinv[node];
    float coef = di * di;
    float4 b = ((const float4*)bias)[lane];
    float4 v0 = h4[(long)node * 32 + lane];
    float4 acc;
    acc.x = coef * v0.x + b.x;
    acc.y = coef * v0.y + b.y;
    acc.z = coef * v0.z + b.z;
    acc.w = coef * v0.w + b.w;

    int beg = g_off[node];
    int end = g_off[node + 1];
    for (int j0 = beg; j0 < end; j0 += 32) {
        int j = j0 + lane;
        int   es = 0;
        float ew = 0.0f;
        if (j < end) { es = g_csr_src[j]; ew = g_csr_w[j]; }
        int cnt = min(32, end - j0);
        for (int i = 0; i < cnt; i++) {
            int   ss = __shfl_sync(0xffffffffu, es, i);
            float ww = __shfl_sync(0xffffffffu, ew, i);
            float4 v = h4[(long)ss * 32 + lane];
            acc.x += ww * v.x;
            acc.y += ww * v.y;
            acc.z += ww * v.z;
            acc.w += ww * v.w;
        }
    }

    ((float4*)agg)[(long)node * 32 + lane] = acc;

    int c = lane * 4;
    atomicAdd(&s_sum[c + 0], acc.x);
    atomicAdd(&s_sum[c + 1], acc.y);
    atomicAdd(&s_sum[c + 2], acc.z);
    atomicAdd(&s_sum[c + 3], acc.w);
    atomicAdd(&s_sq [c + 0], acc.x * acc.x);
    atomicAdd(&s_sq [c + 1], acc.y * acc.y);
    atomicAdd(&s_sq [c + 2], acc.z * acc.z);
    atomicAdd(&s_sq [c + 3], acc.w * acc.w);
    __syncthreads();
    if (tid < DH) {
        atomicAdd(&g_stats[tid],      s_sum[tid]);
        atomicAdd(&g_stats[DH + tid], s_sq [tid]);
    }
}

// ---------------- BN helpers ----------------
__global__ void zero_stats_kernel() {
    int t = threadIdx.x;
    if (t < 2 * DH) g_stats[t] = 0.0f;
}

__global__ void bn_finalize_kernel(const float* __restrict__ gamma,
                                   const float* __restrict__ beta) {
    int t = threadIdx.x;
    if (t >= DH) return;
    float invN = 1.0f / (float)N_NODES;
    float mean = g_stats[t] * invN;
    float var  = g_stats[DH + t] * invN - mean * mean;
    float a = gamma[t] * rsqrtf(var + EPSI);
    g_ab[t]      = a;
    g_ab[DH + t] = beta[t] - mean * a;
}

// ---------------- layer-0 epilogue: BN apply + leaky + (residual + bres) ------
__global__ void act_kernel(const float* __restrict__ agg,
                           const float* __restrict__ res,
                           const float* __restrict__ bres,
                           float* __restrict__ out) {
    int idx = blockIdx.x * blockDim.x + threadIdx.x;
    if (idx >= N_NODES * 32) return;
    int lane = idx & 31;
    float4 a4 = ((const float4*)g_ab)[lane];
    float4 c4 = ((const float4*)g_ab)[32 + lane];
    float4 rb = ((const float4*)bres)[lane];
    float4 v = ((const float4*)agg)[idx];
    float4 r = ((const float4*)res)[idx];
    r.x += rb.x; r.y += rb.y; r.z += rb.z; r.w += rb.w;
    float4 o;
    o.x = a4.x * v.x + c4.x; o.x = (o.x >= 0.f ? o.x : SLOPE * o.x) + r.x;
    o.y = a4.y * v.y + c4.y; o.y = (o.y >= 0.f ? o.y : SLOPE * o.y) + r.y;
    o.z = a4.z * v.z + c4.z; o.z = (o.z >= 0.f ? o.z : SLOPE * o.z) + r.z;
    o.w = a4.w * v.w + c4.w; o.w = (o.w >= 0.f ? o.w : SLOPE * o.w) + r.w;
    ((float4*)out)[idx] = o;
}

// ---------------- layer-1 epilogue fused with final LayerNorm ----------------
__global__ void act_ln_kernel(const float* __restrict__ agg,
                              const float* __restrict__ res,
                              const float* __restrict__ bres,
                              float* __restrict__ out) {
    int row = blockIdx.x * (blockDim.x >> 5) + (threadIdx.x >> 5);
    int lane = threadIdx.x & 31;
    if (row >= N_NODES) return;
    long idx = (long)row * 32 + lane;
    float4 a4 = ((const float4*)g_ab)[lane];
    float4 c4 = ((const float4*)g_ab)[32 + lane];
    float4 rb = ((const float4*)bres)[lane];
    float4 v = ((const float4*)agg)[idx];
    float4 r = ((const float4*)res)[idx];
    r.x += rb.x; r.y += rb.y; r.z += rb.z; r.w += rb.w;
    float4 o;
    o.x = a4.x * v.x + c4.x; o.x = (o.x >= 0.f ? o.x : SLOPE * o.x) + r.x;
    o.y = a4.y * v.y + c4.y; o.y = (o.y >= 0.f ? o.y : SLOPE * o.y) + r.y;
    o.z = a4.z * v.z + c4.z; o.z = (o.z >= 0.f ? o.z : SLOPE * o.z) + r.z;
    o.w = a4.w * v.w + c4.w; o.w = (o.w >= 0.f ? o.w : SLOPE * o.w) + r.w;

    float s  = o.x + o.y + o.z + o.w;
    float s2 = o.x * o.x + o.y * o.y + o.z * o.z + o.w * o.w;
    #pragma unroll
    for (int off = 16; off > 0; off >>= 1) {
        s  += __shfl_xor_sync(0xffffffffu, s,  off);
        s2 += __shfl_xor_sync(0xffffffffu, s2, off);
    }
    float mean = s * (1.0f / DH);
    float var  = s2 * (1.0f / DH) - mean * mean;
    float inv = rsqrtf(var + EPSI);
    float4 wv;
    wv.x = (o.x - mean) * inv;
    wv.y = (o.y - mean) * inv;
    wv.z = (o.z - mean) * inv;
    wv.w = (o.w - mean) * inv;
    ((float4*)out)[idx] = wv;
}

// ---------------- launch ----------------
extern "C" void kernel_launch(void* const* d_in, const int* in_sizes, int n_in,
                              void* d_out, int out_size) {
    const float* x    = (const float*)d_in[0];
    const int*   src  = (const int*)  d_in[1];
    const int*   dst  = (const int*)  d_in[2];
    const float* ew   = (const float*)d_in[3];
    const float* W0   = (const float*)d_in[4];
    const float* b0   = (const float*)d_in[5];
    const float* g0   = (const float*)d_in[6];
    const float* be0  = (const float*)d_in[7];
    const float* W1   = (const float*)d_in[8];
    const float* b1   = (const float*)d_in[9];
    const float* g1   = (const float*)d_in[10];
    const float* be1  = (const float*)d_in[11];
    const float* Wres = (const float*)d_in[12];
    const float* bres = (const float*)d_in[13];
    float* out = (float*)d_out;

    float *gh, *gagg, *gres, *gact;
    cudaGetSymbolAddress((void**)&gh,   g_h);
    cudaGetSymbolAddress((void**)&gagg, g_agg);
    cudaGetSymbolAddress((void**)&gres, g_res);
    cudaGetSymbolAddress((void**)&gact, g_act);

    const int nodeBlocks = (N_NODES + 255) / 256;     // 196
    const int edgeBlocks = (N_EDGES + 255) / 256;
    const int vecBlocks  = (N_NODES * 32 + 255) / 256;
    const int gemmBlocks = (N_NODES + 63) / 64;       // 782
    const int aggBlocks  = N_NODES / 8;               // 6250 exact
    const int lnBlocks   = (N_NODES + 7) / 8;

    // ---- CSR build (shared by both layers) ----
    init_kernel<<<nodeBlocks, 256>>>();
    edge_count_kernel<<<edgeBlocks, 256>>>(dst, ew);
    dinv_kernel<<<nodeBlocks, 256>>>();
    scan_pass1_kernel<<<nodeBlocks, 256>>>();
    scan_pass2_kernel<<<1, 256>>>(nodeBlocks);
    scan_pass3_kernel<<<nodeBlocks, 256>>>();
    fill_kernel<<<edgeBlocks, 256>>>(src, dst, ew);

    // ===== layer 0 =====
    gemm_tc_kernel<DIN><<<gemmBlocks, 256>>>(x, W0, gh, N_NODES);
    gemm_tc_kernel<DIN><<<gemmBlocks, 256>>>(x, Wres, gres, N_NODES);
    zero_stats_kernel<<<1, 256>>>();
    aggregate_kernel<<<aggBlocks, 256>>>(gh, b0, gagg);
    bn_finalize_kernel<<<1, 128>>>(g0, be0);
    act_kernel<<<vecBlocks, 256>>>(gagg, gres, bres, gact);

    // ===== layer 1 =====
    gemm_tc_kernel<DH><<<gemmBlocks, 256>>>(gact, W1, gh, N_NODES);
    zero_stats_kernel<<<1, 256>>>();
    aggregate_kernel<<<aggBlocks, 256>>>(gh, b1, gagg);
    bn_finalize_kernel<<<1, 128>>>(g1, be1);
    act_ln_kernel<<<lnBlocks, 256>>>(gagg, gres, bres, out);
}